// round 12
// baseline (speedup 1.0000x reference)
#include <cuda_runtime.h>
#include <cstdint>

// RecurrentDNNC: y_t = relu(M x_t + B y_{t-1} + c); out_t = sigmoid(W2 y_t + b2)
// Fold-at-load, CHUNK=32: 2048 one-warp blocks (2x warps vs CHUNK=64) for
// latency hiding. Warm window = 64 steps = strips t, t+1; main = strip t+2.

#define SEQ     (1 << 21)
#define BLOCK   32
#define CHUNK   32
#define WARM    64
#define GRID    (SEQ / (BLOCK * CHUNK))  // 2048 blocks
#define NSTRIP  (BLOCK + 2)              // 34 strips: 2 warm-only + 32 chunks
#define NELEM   (NSTRIP * CHUNK)         // 1088 float4 per block
#define NB      17                       // loads per batch (MLP)
#define NBATCH  2                        // 2 * 17 * 32 = 1088

__device__ __forceinline__ float ex2_approx(float x) {
    float r; asm("ex2.approx.f32 %0, %1;" : "=f"(r) : "f"(x)); return r;
}
__device__ __forceinline__ float rcp_approx(float x) {
    float r; asm("rcp.approx.f32 %0, %1;" : "=f"(r) : "f"(x)); return r;
}

__global__ void __launch_bounds__(BLOCK, 12)
rdnnc_kernel(const float4* __restrict__ x,
             const float*  __restrict__ W1, const float* __restrict__ b1,
             const float*  __restrict__ Wd, const float* __restrict__ bd,
             const float*  __restrict__ W2, const float* __restrict__ b2,
             float4*       __restrict__ out4)
{
    // folded inputs, transposed: [strip][step], +1 float2 pad per row
    // (row stride 33*8B -> 2-bank shift/strip; conflict-free per 16-lane phase)
    __shared__ float2 ss[NSTRIP][CHUNK + 1];   // ~9 KB
    __shared__ float4 so[BLOCK * 8];           // 4 KB out staging (16-step segs)

    const int tid        = threadIdx.x;
    const int blockStart = (int)blockIdx.x * (BLOCK * CHUNK);
    const int blockBase  = blockStart - WARM;           // step of element e=0

    // ---- fold parameters (tiny L1/L2-resident loads) ----
    const float A00 = Wd[0], A01 = Wd[1], B00 = Wd[2], B01 = Wd[3];
    const float A10 = Wd[4], A11 = Wd[5], B10 = Wd[6], B11 = Wd[7];

    const float M00 = A00*W1[0] + A01*W1[4];
    const float M01 = A00*W1[1] + A01*W1[5];
    const float M02 = A00*W1[2] + A01*W1[6];
    const float M03 = A00*W1[3] + A01*W1[7];
    const float M10 = A10*W1[0] + A11*W1[4];
    const float M11 = A10*W1[1] + A11*W1[5];
    const float M12 = A10*W1[2] + A11*W1[6];
    const float M13 = A10*W1[3] + A11*W1[7];

    const float c0 = A00*b1[0] + A01*b1[1] + bd[0];
    const float c1 = A10*b1[0] + A11*b1[1] + bd[1];

    const float L2E = 1.4426950408889634f;
    const float w00 = -L2E*W2[0], w01 = -L2E*W2[1];
    const float w10 = -L2E*W2[2], w11 = -L2E*W2[3];
    const float v0  = -L2E*b2[0], v1  = -L2E*b2[1];

    // ---- fold phase: batched coalesced LDG.128 (MLP=17) -> 8 FFMA -> STS.64
    #pragma unroll
    for (int i = 0; i < NBATCH; ++i) {
        float4 q[NB];
        #pragma unroll
        for (int b = 0; b < NB; ++b) {
            const int e = (i * NB + b) * BLOCK + tid;    // coalesced per load
            int g = blockBase + e;
            if (g < 0) g = 0;                            // block 0 head: unused
            q[b] = x[g];
        }
        #pragma unroll
        for (int b = 0; b < NB; ++b) {
            const int e = (i * NB + b) * BLOCK + tid;
            const float s0 = fmaf(M00,q[b].x, fmaf(M01,q[b].y, fmaf(M02,q[b].z, fmaf(M03,q[b].w, c0))));
            const float s1 = fmaf(M10,q[b].x, fmaf(M11,q[b].y, fmaf(M12,q[b].z, fmaf(M13,q[b].w, c1))));
            ss[e >> 5][e & 31] = make_float2(s0, s1);
        }
    }
    __syncthreads();                                      // 1 warp: cheap

    // ---- recurrence ----
    float y0_ = 0.f, y1_ = 0.f;
    auto step = [&](const float2 s) {
        const float n0 = fmaxf(fmaf(B00,y0_, fmaf(B01,y1_, s.x)), 0.f);
        const float n1 = fmaxf(fmaf(B10,y0_, fmaf(B11,y1_, s.y)), 0.f);
        y0_ = n0; y1_ = n1;
    };

    // warm: strips tid (steps -64..-33) and tid+1 (-32..-1), each exactly
    // guarded so out-of-range prefixes keep the true y=0 start.
    const int myStart = blockStart + tid * CHUNK;
    if (myStart - 64 >= 0) {
        #pragma unroll 8
        for (int j = 0; j < CHUNK; ++j) step(ss[tid][j]);
    }
    if (myStart - 32 >= 0) {
        #pragma unroll 8
        for (int j = 0; j < CHUNK; ++j) step(ss[tid + 1][j]);
    }

    // main: strip tid+2; head + swizzled staging, drain every 16 steps
    const int sm     = tid + 2;
    const int o4base = (int)blockIdx.x * 512;    // block covers 512 float4 of out

    #pragma unroll
    for (int seg = 0; seg < 2; ++seg) {
        #pragma unroll
        for (int p = 0; p < 8; ++p) {             // p = float4 (2-step pair) in segment
            step(ss[sm][seg*16 + 2*p]);
            const float z0 = fmaf(w00,y0_, fmaf(w01,y1_, v0));
            const float z1 = fmaf(w10,y0_, fmaf(w11,y1_, v1));
            const float r0 = rcp_approx(1.f + ex2_approx(z0));
            const float r1 = rcp_approx(1.f + ex2_approx(z1));

            step(ss[sm][seg*16 + 2*p + 1]);
            const float z2 = fmaf(w00,y0_, fmaf(w01,y1_, v0));
            const float z3 = fmaf(w10,y0_, fmaf(w11,y1_, v1));
            const float r2 = rcp_approx(1.f + ex2_approx(z2));
            const float r3 = rcp_approx(1.f + ex2_approx(z3));

            so[tid * 8 + ((tid ^ p) & 7)] = make_float4(r0, r1, r2, r3);
        }
        __syncwarp();

        #pragma unroll
        for (int l = 0; l < 8; ++l) {             // drain: 128B contiguous per strip
            const int e = l * BLOCK + tid;
            const int u = e >> 3;
            const int p = e & 7;
            out4[o4base + u * 16 + seg * 8 + p] = so[u * 8 + ((u ^ p) & 7)];
        }
        __syncwarp();
    }
}

extern "C" void kernel_launch(void* const* d_in, const int* in_sizes, int n_in,
                              void* d_out, int out_size)
{
    rdnnc_kernel<<<GRID, BLOCK>>>(
        (const float4*)d_in[0],
        (const float*)d_in[1], (const float*)d_in[2],
        (const float*)d_in[3], (const float*)d_in[4],
        (const float*)d_in[5], (const float*)d_in[6],
        (float4*)d_out);
}

// round 13
// speedup vs baseline: 1.0283x; 1.0283x over previous
#include <cuda_runtime.h>
#include <cstdint>

// RecurrentDNNC: y_t = relu(M x_t + B y_{t-1} + c); out_t = sigmoid(W2 y_t + b2)
// Fold-at-load with intra-block cp.async stage pipeline: x window (33 strips x
// 64 steps) streamed in 8 step-slices through 3 rotating buffers; fold+warm of
// slice q overlaps loads of slices q+1..q+3 -> continuous DRAM supply.
// CHUNK=64, 1-warp blocks, 1024 blocks (R10 geometry).

#define SEQ     (1 << 21)
#define BLOCK   32
#define CHUNK   64
#define WARM    64                        // == CHUNK: warm window = neighbor strip
#define GRID    (SEQ / (BLOCK * CHUNK))   // 1024 blocks
#define NSTRIP  (BLOCK + 1)               // strips -1..31 (s=0 is warm-only)
#define STAGE   8                         // steps per slice
#define NSTAGE  (CHUNK / STAGE)           // 8 slices
#define RAWS    (NSTRIP * STAGE)          // 264 float4 per slice
#define NBUF    3                         // rotating raw buffers

// smem layout (bytes):
//   [0, 12672)       rx: float4 raw slices [NBUF][RAWS]   (dead after stage loop)
//   [0, 4096)        so: float4 out staging (aliases rx, used only in main)
//   [12672, 29832)   ss: float2 folded [NSTRIP][CHUNK+1]
#define RX_BYTES   (NBUF * RAWS * 16)     // 12672
#define SS_OFF     RX_BYTES
#define SMEM_BYTES (SS_OFF + NSTRIP * (CHUNK + 1) * 8)   // 29832

__device__ __forceinline__ float ex2_approx(float x) {
    float r; asm("ex2.approx.f32 %0, %1;" : "=f"(r) : "f"(x)); return r;
}
__device__ __forceinline__ float rcp_approx(float x) {
    float r; asm("rcp.approx.f32 %0, %1;" : "=f"(r) : "f"(x)); return r;
}
__device__ __forceinline__ void cp_async16(uint32_t dst, const void* src) {
    asm volatile("cp.async.cg.shared.global [%0], [%1], 16;" :: "r"(dst), "l"(src));
}
__device__ __forceinline__ void cp_commit() { asm volatile("cp.async.commit_group;"); }
__device__ __forceinline__ void cp_wait2()  { asm volatile("cp.async.wait_group 2;"); }

__global__ void __launch_bounds__(BLOCK, 7)
rdnnc_kernel(const float4* __restrict__ x,
             const float*  __restrict__ W1, const float* __restrict__ b1,
             const float*  __restrict__ Wd, const float* __restrict__ bd,
             const float*  __restrict__ W2, const float* __restrict__ b2,
             float4*       __restrict__ out4)
{
    __shared__ __align__(16) char smem[SMEM_BYTES];
    float2 (*ss)[CHUNK + 1] = reinterpret_cast<float2(*)[CHUNK + 1]>(smem + SS_OFF);
    float4* so              = reinterpret_cast<float4*>(smem);          // aliases rx
    const uint32_t rx_base  = (uint32_t)__cvta_generic_to_shared(smem);

    const int tid       = threadIdx.x;
    const int blockBase = (int)blockIdx.x * (BLOCK * CHUNK) - WARM;     // step of (s=0,j=0)

    // issue one slice into buffer buf (coalesced: 8 consecutive float4 per strip)
    auto issue_slice = [&](int q, int buf) {
        const uint32_t bb = rx_base + (uint32_t)buf * (RAWS * 16);
        #pragma unroll
        for (int k = 0; k < 9; ++k) {
            const int slot = k * BLOCK + tid;
            if (slot < RAWS) {
                const int s  = slot >> 3;
                const int jj = slot & 7;
                int g = blockBase + s * CHUNK + q * STAGE + jj;
                if (g < 0) g = 0;                      // block 0, strip 0: value unused
                cp_async16(bb + (uint32_t)(slot << 4), x + g);
            }
        }
    };

    // ---- start loads IMMEDIATELY (params fold overlaps the first waits) ----
    issue_slice(0, 0); cp_commit();
    issue_slice(1, 1); cp_commit();
    issue_slice(2, 2); cp_commit();

    // ---- fold parameters (tiny L1/L2-resident loads) ----
    const float A00 = Wd[0], A01 = Wd[1], B00 = Wd[2], B01 = Wd[3];
    const float A10 = Wd[4], A11 = Wd[5], B10 = Wd[6], B11 = Wd[7];

    const float M00 = A00*W1[0] + A01*W1[4];
    const float M01 = A00*W1[1] + A01*W1[5];
    const float M02 = A00*W1[2] + A01*W1[6];
    const float M03 = A00*W1[3] + A01*W1[7];
    const float M10 = A10*W1[0] + A11*W1[4];
    const float M11 = A10*W1[1] + A11*W1[5];
    const float M12 = A10*W1[2] + A11*W1[6];
    const float M13 = A10*W1[3] + A11*W1[7];

    const float c0 = A00*b1[0] + A01*b1[1] + bd[0];
    const float c1 = A10*b1[0] + A11*b1[1] + bd[1];

    const float L2E = 1.4426950408889634f;
    const float w00 = -L2E*W2[0], w01 = -L2E*W2[1];
    const float w10 = -L2E*W2[2], w11 = -L2E*W2[3];
    const float v0  = -L2E*b2[0], v1  = -L2E*b2[1];

    float y0_ = 0.f, y1_ = 0.f;
    auto step = [&](const float2 s) {
        const float n0 = fmaxf(fmaf(B00,y0_, fmaf(B01,y1_, s.x)), 0.f);
        const float n1 = fmaxf(fmaf(B10,y0_, fmaf(B11,y1_, s.y)), 0.f);
        y0_ = n0; y1_ = n1;
    };

    const bool do_warm = (blockIdx.x | tid) != 0;   // thread 0 / block 0: exact y=0 start

    // ---- stage loop: wait -> fold slice -> warm-advance -> issue slice+3 ----
    for (int q = 0; q < NSTAGE; ++q) {
        const int buf = q % NBUF;
        cp_wait2();            // our own groups: slice q landed (pending <= 2)
        __syncwarp();          // all lanes past their waits -> whole slice visible

        const float4* rx = reinterpret_cast<const float4*>(smem) + buf * RAWS;
        #pragma unroll
        for (int k = 0; k < 9; ++k) {
            const int slot = k * BLOCK + tid;
            if (slot < RAWS) {
                const float4 v = rx[slot];
                const int s = slot >> 3;
                const int j = q * STAGE + (slot & 7);
                const float s0 = fmaf(M00,v.x, fmaf(M01,v.y, fmaf(M02,v.z, fmaf(M03,v.w, c0))));
                const float s1 = fmaf(M10,v.x, fmaf(M11,v.y, fmaf(M12,v.z, fmaf(M13,v.w, c1))));
                ss[s][j] = make_float2(s0, s1);
            }
        }
        __syncwarp();          // folds visible before warm reads

        if (do_warm) {         // warm: strip tid, steps of this slice
            #pragma unroll
            for (int jj = 0; jj < STAGE; ++jj) step(ss[tid][q * STAGE + jj]);
        }

        if (q + NBUF < NSTAGE) issue_slice(q + NBUF, buf);
        cp_commit();           // empty group when nothing issued: keeps wait invariant
    }
    __syncwarp();              // rx dead from here; so[] may alias it

    // ---- main: strip tid+1; head + swizzled staging, drain every 16 steps ----
    const int sm     = tid + 1;
    const int o4base = (int)blockIdx.x * 1024;      // block covers 1024 float4 of out

    #pragma unroll
    for (int seg = 0; seg < 4; ++seg) {
        #pragma unroll
        for (int p = 0; p < 8; ++p) {               // p = float4 (2-step pair) in segment
            step(ss[sm][seg*16 + 2*p]);
            const float z0 = fmaf(w00,y0_, fmaf(w01,y1_, v0));
            const float z1 = fmaf(w10,y0_, fmaf(w11,y1_, v1));
            const float r0 = rcp_approx(1.f + ex2_approx(z0));
            const float r1 = rcp_approx(1.f + ex2_approx(z1));

            step(ss[sm][seg*16 + 2*p + 1]);
            const float z2 = fmaf(w00,y0_, fmaf(w01,y1_, v0));
            const float z3 = fmaf(w10,y0_, fmaf(w11,y1_, v1));
            const float r2 = rcp_approx(1.f + ex2_approx(z2));
            const float r3 = rcp_approx(1.f + ex2_approx(z3));

            so[tid * 8 + ((tid ^ p) & 7)] = make_float4(r0, r1, r2, r3);
        }
        __syncwarp();

        #pragma unroll
        for (int l = 0; l < 8; ++l) {               // drain: 128B contiguous per strip
            const int e = l * BLOCK + tid;
            const int u = e >> 3;
            const int p = e & 7;
            out4[o4base + u * 32 + seg * 8 + p] = so[u * 8 + ((u ^ p) & 7)];
        }
        __syncwarp();
    }
}

extern "C" void kernel_launch(void* const* d_in, const int* in_sizes, int n_in,
                              void* d_out, int out_size)
{
    rdnnc_kernel<<<GRID, BLOCK>>>(
        (const float4*)d_in[0],
        (const float*)d_in[1], (const float*)d_in[2],
        (const float*)d_in[3], (const float*)d_in[4],
        (const float*)d_in[5], (const float*)d_in[6],
        (float4*)d_out);
}

// round 14
// speedup vs baseline: 1.2097x; 1.1765x over previous
#include <cuda_runtime.h>
#include <cstdint>

// RecurrentDNNC: y_t = relu(M x_t + B y_{t-1} + c); out_t = sigmoid(W2 y_t + b2)
// CHUNK=WARM=32: 2048 one-warp blocks (~14/SM), 2 steps per output (same work
// ratio as best kernel) with half the per-block serial chain. Warm = strip tid,
// main = strip tid+1. Fold-at-load with register-MLP batched LDG (R10 style).

#define SEQ     (1 << 21)
#define BLOCK   32
#define CHUNK   32
#define WARM    32                       // == CHUNK: warm window = neighbor strip
#define GRID    (SEQ / (BLOCK * CHUNK))  // 2048 blocks
#define NSTRIP  (BLOCK + 1)              // strips -1..31
#define NELEM   (NSTRIP * CHUNK)         // 1056 float4 per block
#define NB      11                       // loads per batch (MLP)
#define NBATCH  3                        // 3 * 11 * 32 = 1056

__device__ __forceinline__ float ex2_approx(float x) {
    float r; asm("ex2.approx.f32 %0, %1;" : "=f"(r) : "f"(x)); return r;
}
__device__ __forceinline__ float rcp_approx(float x) {
    float r; asm("rcp.approx.f32 %0, %1;" : "=f"(r) : "f"(x)); return r;
}

__global__ void __launch_bounds__(BLOCK, 14)
rdnnc_kernel(const float4* __restrict__ x,
             const float*  __restrict__ W1, const float* __restrict__ b1,
             const float*  __restrict__ Wd, const float* __restrict__ bd,
             const float*  __restrict__ W2, const float* __restrict__ b2,
             float4*       __restrict__ out4)
{
    // folded inputs, transposed: [strip][step], +1 float2 pad per row
    // (row stride 33*8B -> 2-bank shift/strip; conflict-free per 16-lane phase)
    __shared__ float2 ss[NSTRIP][CHUNK + 1];   // ~8.7 KB
    __shared__ float4 so[BLOCK * 8];           // 4 KB out staging (16-step segs)

    const int tid       = threadIdx.x;
    const int blockBase = (int)blockIdx.x * (BLOCK * CHUNK) - WARM;  // step of e=0

    // ---- fold parameters (tiny L1/L2-resident loads) ----
    const float A00 = Wd[0], A01 = Wd[1], B00 = Wd[2], B01 = Wd[3];
    const float A10 = Wd[4], A11 = Wd[5], B10 = Wd[6], B11 = Wd[7];

    const float M00 = A00*W1[0] + A01*W1[4];
    const float M01 = A00*W1[1] + A01*W1[5];
    const float M02 = A00*W1[2] + A01*W1[6];
    const float M03 = A00*W1[3] + A01*W1[7];
    const float M10 = A10*W1[0] + A11*W1[4];
    const float M11 = A10*W1[1] + A11*W1[5];
    const float M12 = A10*W1[2] + A11*W1[6];
    const float M13 = A10*W1[3] + A11*W1[7];

    const float c0 = A00*b1[0] + A01*b1[1] + bd[0];
    const float c1 = A10*b1[0] + A11*b1[1] + bd[1];

    const float L2E = 1.4426950408889634f;
    const float w00 = -L2E*W2[0], w01 = -L2E*W2[1];
    const float w10 = -L2E*W2[2], w11 = -L2E*W2[3];
    const float v0  = -L2E*b2[0], v1  = -L2E*b2[1];

    // ---- fold phase: batched coalesced LDG.128 (MLP=11) -> 8 FFMA -> STS.64
    #pragma unroll
    for (int bt = 0; bt < NBATCH; ++bt) {
        float4 q[NB];
        #pragma unroll
        for (int b = 0; b < NB; ++b) {
            const int e = (bt * NB + b) * BLOCK + tid;   // coalesced per load
            int g = blockBase + e;
            if (g < 0) g = 0;                            // block 0, strip -1: unused
            q[b] = x[g];
        }
        #pragma unroll
        for (int b = 0; b < NB; ++b) {
            const int e = (bt * NB + b) * BLOCK + tid;
            const float s0 = fmaf(M00,q[b].x, fmaf(M01,q[b].y, fmaf(M02,q[b].z, fmaf(M03,q[b].w, c0))));
            const float s1 = fmaf(M10,q[b].x, fmaf(M11,q[b].y, fmaf(M12,q[b].z, fmaf(M13,q[b].w, c1))));
            ss[e >> 5][e & 31] = make_float2(s0, s1);
        }
    }
    __syncthreads();                                      // 1 warp: cheap

    // ---- recurrence ----
    float y0_ = 0.f, y1_ = 0.f;
    auto step = [&](const float2 s) {
        const float n0 = fmaxf(fmaf(B00,y0_, fmaf(B01,y1_, s.x)), 0.f);
        const float n1 = fmaxf(fmaf(B10,y0_, fmaf(B11,y1_, s.y)), 0.f);
        y0_ = n0; y1_ = n1;
    };

    // warm: strip tid (= previous 32 steps). Block 0 / thread 0: exact y=0 start.
    if ((blockIdx.x | tid) != 0) {
        #pragma unroll 8
        for (int j = 0; j < WARM; ++j) step(ss[tid][j]);
    }

    // main: strip tid+1; head + swizzled staging, drain every 16 steps (128B runs)
    const int sm     = tid + 1;
    const int o4base = (int)blockIdx.x * 512;    // block covers 512 float4 of out

    #pragma unroll
    for (int seg = 0; seg < 2; ++seg) {
        #pragma unroll
        for (int p = 0; p < 8; ++p) {             // p = float4 (2-step pair) in segment
            step(ss[sm][seg*16 + 2*p]);
            const float z0 = fmaf(w00,y0_, fmaf(w01,y1_, v0));
            const float z1 = fmaf(w10,y0_, fmaf(w11,y1_, v1));
            const float r0 = rcp_approx(1.f + ex2_approx(z0));
            const float r1 = rcp_approx(1.f + ex2_approx(z1));

            step(ss[sm][seg*16 + 2*p + 1]);
            const float z2 = fmaf(w00,y0_, fmaf(w01,y1_, v0));
            const float z3 = fmaf(w10,y0_, fmaf(w11,y1_, v1));
            const float r2 = rcp_approx(1.f + ex2_approx(z2));
            const float r3 = rcp_approx(1.f + ex2_approx(z3));

            so[tid * 8 + ((tid ^ p) & 7)] = make_float4(r0, r1, r2, r3);
        }
        __syncwarp();

        #pragma unroll
        for (int l = 0; l < 8; ++l) {             // drain: 128B contiguous per strip
            const int e = l * BLOCK + tid;
            const int u = e >> 3;                 // strip (16 float4 of out each)
            const int p = e & 7;
            out4[o4base + u * 16 + seg * 8 + p] = so[u * 8 + ((u ^ p) & 7)];
        }
        __syncwarp();
    }
}

extern "C" void kernel_launch(void* const* d_in, const int* in_sizes, int n_in,
                              void* d_out, int out_size)
{
    rdnnc_kernel<<<GRID, BLOCK>>>(
        (const float4*)d_in[0],
        (const float*)d_in[1], (const float*)d_in[2],
        (const float*)d_in[3], (const float*)d_in[4],
        (const float*)d_in[5], (const float*)d_in[6],
        (float4*)d_out);
}